// round 13
// baseline (speedup 1.0000x reference)
#include <cuda_runtime.h>
#include <cuda_fp16.h>

#define NMAX 100000
#define EMAX 1700000
#define FDIM 128
#define HDIM 64

// ---------------- scratch (static device globals; no runtime alloc) -------
__device__ int    d_is32;                // 1 if edge buffers are int32
__device__ int    d_deg[NMAX];
__device__ float  d_dinv[NMAX];
__device__ __half d_Gh  [NMAX * HDIM];   // g1, then g2 (fp16 messages)
__device__ float  d_ACC [NMAX * HDIM];   // acc1 (seeded with g1), f32
__device__ float  d_ACC2[NMAX * HDIM];   // acc2 (seeded with g2), f32
__device__ __half d_Hh  [NMAX * HDIM];   // H2 in fp16 (gemm3 A-loader side-store)
__device__ __half d_TDh [NMAX * HDIM];   // TD = H2 @ Wb^T in fp16
__device__ float  d_Wc  [FDIM * HDIM];   // W0 @ W1
__device__ float  d_bc  [HDIM];          // b0 @ W1
__device__ float  d_WbT [HDIM * HDIM];   // Wb[0]^T

// ---------------- vector reduction helper ----------------------------------
__device__ __forceinline__ void red_add_v4(float* p, float4 v) {
#if __CUDA_ARCH__ >= 900
    asm volatile("red.global.add.v4.f32 [%0], {%1, %2, %3, %4};"
                 :: "l"(p), "f"(v.x), "f"(v.y), "f"(v.z), "f"(v.w)
                 : "memory");
#else
    atomicAdd(p + 0, v.x); atomicAdd(p + 1, v.y);
    atomicAdd(p + 2, v.z); atomicAdd(p + 3, v.w);
#endif
}

// ---------------- init: zero deg + dtype detect (fused) ---------------------
__global__ void __launch_bounds__(256) k_init(const unsigned int* __restrict__ w,
                                              int nwords2, int n) {
    int i = blockIdx.x * blockDim.x + threadIdx.x;
    if (i == 0) d_is32 = 0;
    if (i < n) d_deg[i] = 0;
    int idx = 2 * i + 1;
    if (i < 2048 && idx < nwords2 && w[idx] != 0u) d_is32 = 1;
}

// ---------------- degree count (raw edge buffer, targets only) --------------
__global__ void __launch_bounds__(256) k_deg(const int* __restrict__ buf, int E) {
    int i = blockIdx.x * blockDim.x + threadIdx.x;
    if (i >= E) return;
    int v = d_is32 ? buf[E + i] : buf[2 * (E + i)];
    atomicAdd(&d_deg[v], 1);
}

__global__ void __launch_bounds__(256) k_dinv(int n) {
    int i = blockIdx.x * blockDim.x + threadIdx.x;
    if (i < n) d_dinv[i] = rsqrtf((float)(d_deg[i] + 1));  // +1 self loop
}

// ---------------- weight prep: Wc = W0@W1, bc = b0@W1, WbT (MLP=4) --------
__global__ void __launch_bounds__(256) k_prep(const float* __restrict__ W0,
                                              const float* __restrict__ b0,
                                              const float* __restrict__ W1,
                                              const float* __restrict__ Wb) {
    int t = blockIdx.x * blockDim.x + threadIdx.x;
    if (t < FDIM * HDIM) {
        int k = t / HDIM, o = t % HDIM;
        float s0 = 0.f, s1 = 0.f, s2 = 0.f, s3 = 0.f;
        #pragma unroll 4
        for (int m = 0; m < FDIM; m += 4) {
            s0 += W0[k * FDIM + m + 0] * W1[(m + 0) * HDIM + o];
            s1 += W0[k * FDIM + m + 1] * W1[(m + 1) * HDIM + o];
            s2 += W0[k * FDIM + m + 2] * W1[(m + 2) * HDIM + o];
            s3 += W0[k * FDIM + m + 3] * W1[(m + 3) * HDIM + o];
        }
        d_Wc[t] = (s0 + s1) + (s2 + s3);
    }
    if (t < HDIM) {
        float s = 0.f;
        for (int m = 0; m < FDIM; m++) s += b0[m] * W1[m * HDIM + t];
        d_bc[t] = s;
    }
    if (t < HDIM * HDIM) {
        int i = t / HDIM, j = t % HDIM;
        d_WbT[j * HDIM + i] = Wb[t];   // WbT[j][i] = Wb[i][j]
    }
}

// ---------------- fused GEMM: C[M,64] = f(A)[M,K] @ B[K,64] ---------------
// BM=256 rows/block, 256 threads, 8x8 micro-tile (2 FLOP per LDS byte).
// MODE 0: A = Ain (x), B = d_Wc.  C = (A@B + bc)*dinv -> d_Gh fp16 + d_ACC seed
// MODE 1: A = relu(dinv*acc1 + b1) in loader, B = Bin (W2).
//         C = (A@B)*dinv -> d_Gh fp16 + d_ACC2 seed
// MODE 2: A = dinv*acc2 + b2 = H2 in loader (side-store fp16 d_Hh), B = d_WbT.
//         C = A@B -> d_TDh fp16
template <int K, int MODE>
__global__ void __launch_bounds__(256) gemmF(const float* __restrict__ Ain,
                                             const float* __restrict__ Bin,
                                             const float* __restrict__ bA,
                                             int M) {
    const float* Bsrc = (MODE == 0) ? d_Wc : (MODE == 2) ? d_WbT : Bin;

    __shared__ float As[16][268];    // [k][row], padded
    __shared__ float Bs[16][72];     // [k][col], padded
    const int tid = threadIdx.x;
    const int mg  = tid >> 3;        // 0..31: rows mg*8..mg*8+7
    const int ng  = tid & 7;         // 0..7:  cols ng*8..ng*8+7
    const int bm  = blockIdx.x * 256;

    float acc[8][8] = {};

    for (int kc = 0; kc < K; kc += 16) {
        // ---- load A chunk (256 rows x 16 k): 4 float4 per thread, fused f()
        float4 av[4];
        #pragma unroll
        for (int p = 0; p < 4; p++) {
            int idx  = p * 256 + tid;
            int row  = idx >> 2;
            int lk   = (idx & 3) << 2;
            int grow = bm + row;
            float4 v = make_float4(0.f, 0.f, 0.f, 0.f);
            if (grow < M) {
                if (MODE == 0) {
                    v = *(const float4*)(Ain + (size_t)grow * K + kc + lk);
                } else {
                    const float* accsrc = (MODE == 1) ? d_ACC : d_ACC2;
                    float4 a4 = *(const float4*)(accsrc + (size_t)grow * 64 + kc + lk);
                    float4 bv = *(const float4*)(bA + kc + lk);
                    float s = d_dinv[grow];
                    v.x = s * a4.x + bv.x;
                    v.y = s * a4.y + bv.y;
                    v.z = s * a4.z + bv.z;
                    v.w = s * a4.w + bv.w;
                    if (MODE == 1) {
                        v.x = fmaxf(v.x, 0.f); v.y = fmaxf(v.y, 0.f);
                        v.z = fmaxf(v.z, 0.f); v.w = fmaxf(v.w, 0.f);
                    }
                    if (MODE == 2) {   // side-store H2 fp16 (once per element)
                        __half2 h01 = __floats2half2_rn(v.x, v.y);
                        __half2 h23 = __floats2half2_rn(v.z, v.w);
                        uint2 pk = make_uint2(*(unsigned*)&h01, *(unsigned*)&h23);
                        *(uint2*)(d_Hh + (size_t)grow * 64 + kc + lk) = pk;
                    }
                }
            }
            av[p] = v;
        }
        // ---- load B chunk (16 k x 64): 1 float4 per thread
        int bk = tid >> 4, bc4 = (tid & 15) << 2;
        float4 bvv = *(const float4*)(Bsrc + (size_t)(kc + bk) * 64 + bc4);

        __syncthreads();               // previous chunk consumed
        #pragma unroll
        for (int p = 0; p < 4; p++) {
            int idx = p * 256 + tid;
            int row = idx >> 2;
            int lk  = (idx & 3) << 2;
            As[lk + 0][row] = av[p].x;
            As[lk + 1][row] = av[p].y;
            As[lk + 2][row] = av[p].z;
            As[lk + 3][row] = av[p].w;
        }
        *(float4*)&Bs[bk][bc4] = bvv;
        __syncthreads();

        #pragma unroll
        for (int k = 0; k < 16; k++) {
            float4 a0 = *(const float4*)&As[k][mg * 8];
            float4 a1 = *(const float4*)&As[k][mg * 8 + 4];
            float4 b0 = *(const float4*)&Bs[k][ng * 8];
            float4 b1 = *(const float4*)&Bs[k][ng * 8 + 4];
            float a[8] = {a0.x, a0.y, a0.z, a0.w, a1.x, a1.y, a1.z, a1.w};
            float b[8] = {b0.x, b0.y, b0.z, b0.w, b1.x, b1.y, b1.z, b1.w};
            #pragma unroll
            for (int i = 0; i < 8; i++)
                #pragma unroll
                for (int j = 0; j < 8; j++)
                    acc[i][j] += a[i] * b[j];
        }
    }

    // ---- epilogue: rows bm+mg*8+i, cols ng*8..ng*8+7
    #pragma unroll
    for (int i = 0; i < 8; i++) {
        int r = bm + mg * 8 + i;
        if (r >= M) continue;
        float s = (MODE == 2) ? 1.f : d_dinv[r];
        float o8[8];
        #pragma unroll
        for (int j = 0; j < 8; j++) {
            float v = acc[i][j];
            if (MODE == 0) v += d_bc[ng * 8 + j];
            o8[j] = v * s;
        }
        size_t off = (size_t)r * 64 + ng * 8;
        __half2 h01 = __floats2half2_rn(o8[0], o8[1]);
        __half2 h23 = __floats2half2_rn(o8[2], o8[3]);
        __half2 h45 = __floats2half2_rn(o8[4], o8[5]);
        __half2 h67 = __floats2half2_rn(o8[6], o8[7]);
        uint4 pk = make_uint4(*(unsigned*)&h01, *(unsigned*)&h23,
                              *(unsigned*)&h45, *(unsigned*)&h67);
        if (MODE == 0 || MODE == 1) {
            *(uint4*)(d_Gh + off) = pk;                       // fp16 messages
            float* accdst = (MODE == 0) ? d_ACC : d_ACC2;
            *(float4*)(accdst + off)     = make_float4(o8[0], o8[1], o8[2], o8[3]);
            *(float4*)(accdst + off + 4) = make_float4(o8[4], o8[5], o8[6], o8[7]);
        } else {
            *(uint4*)(d_TDh + off) = pk;                      // TD fp16
        }
    }
}

// ---------------- edge scatter-add: acc[col] += g[row] --------------------
// 16 threads/edge: gather 4 halves (8B), convert, ONE red.v4.f32 (16B).
template <int WHICH>   // 1 -> d_ACC, 2 -> d_ACC2
__global__ void __launch_bounds__(256) k_scatter(const int* __restrict__ buf, int E) {
    const int is32 = d_is32;
    int total = E * 16;
    for (int t = blockIdx.x * blockDim.x + threadIdx.x; t < total;
         t += gridDim.x * blockDim.x) {
        int e = t >> 4, c = t & 15;
        int r  = __ldg(&buf[is32 ? e : 2 * e]);
        int cl = __ldg(&buf[is32 ? (E + e) : 2 * (E + e)]);
        uint2 pk = __ldg((const uint2*)(d_Gh + (size_t)r * 64 + c * 4));
        float2 f01 = __half22float2(*(__half2*)&pk.x);
        float2 f23 = __half22float2(*(__half2*)&pk.y);
        float4 v = make_float4(f01.x, f01.y, f23.x, f23.y);
        float* p = (WHICH == 1 ? d_ACC : d_ACC2) + (size_t)cl * 64 + c * 4;
        red_add_v4(p, v);
    }
}

// ---------------- bilinear decoder: out[e] = H2[src]·TD[dst] + bb ---------
__global__ void __launch_bounds__(256) k_bilinear(const int* __restrict__ buf, int E,
                                                  const float* __restrict__ bb,
                                                  float* __restrict__ out) {
    const int is32 = d_is32;
    const float bias = bb[0];
    const uint4* Hp = (const uint4*)d_Hh;    // 8 halves per uint4
    const uint4* Tp = (const uint4*)d_TDh;
    int total = E * 8;
    for (int t = blockIdx.x * blockDim.x + threadIdx.x; t < total;
         t += gridDim.x * blockDim.x) {
        int e = t >> 3, c = t & 7;
        int s = __ldg(&buf[is32 ? e : 2 * e]);
        int d = __ldg(&buf[is32 ? (E + e) : 2 * (E + e)]);
        uint4 a = __ldg(Hp + (size_t)s * 8 + c);
        uint4 b = __ldg(Tp + (size_t)d * 8 + c);
        float p = 0.f;
        {
            float2 fa, fb;
            fa = __half22float2(*(__half2*)&a.x); fb = __half22float2(*(__half2*)&b.x);
            p += fa.x * fb.x + fa.y * fb.y;
            fa = __half22float2(*(__half2*)&a.y); fb = __half22float2(*(__half2*)&b.y);
            p += fa.x * fb.x + fa.y * fb.y;
            fa = __half22float2(*(__half2*)&a.z); fb = __half22float2(*(__half2*)&b.z);
            p += fa.x * fb.x + fa.y * fb.y;
            fa = __half22float2(*(__half2*)&a.w); fb = __half22float2(*(__half2*)&b.w);
            p += fa.x * fb.x + fa.y * fb.y;
        }
        p += __shfl_xor_sync(0xffffffffu, p, 4);
        p += __shfl_xor_sync(0xffffffffu, p, 2);
        p += __shfl_xor_sync(0xffffffffu, p, 1);
        if (c == 0) out[e] = p + bias;
    }
}

// ---------------- launcher: kernel launches ONLY ---------------------------
extern "C" void kernel_launch(void* const* d_in, const int* in_sizes, int n_in,
                              void* d_out, int out_size) {
    const float* x     = (const float*)d_in[0];
    const int*   eip   = (const int*)d_in[1];    // prediction edges (raw words)
    const int*   eipos = (const int*)d_in[2];    // message edges (raw words)
    const float* W0    = (const float*)d_in[3];
    const float* b0    = (const float*)d_in[4];
    const float* W1    = (const float*)d_in[5];
    const float* b1    = (const float*)d_in[6];
    const float* W2    = (const float*)d_in[7];
    const float* b2    = (const float*)d_in[8];
    const float* Wb    = (const float*)d_in[9];
    const float* bb    = (const float*)d_in[10];
    float* out = (float*)d_out;

    const int N     = in_sizes[0] / FDIM;
    const int Epred = in_sizes[1] / 2;
    const int Epos  = in_sizes[2] / 2;
    const int GS    = 8192;

    // init (zero deg + dtype detect), degree from raw buffer, dinv
    k_init<<<(N + 255) / 256, 256>>>((const unsigned int*)eip, 2 * Epred, N);
    k_deg<<<(Epos + 255) / 256, 256>>>(eipos, Epos);
    k_dinv<<<(N + 255) / 256, 256>>>(N);

    // weight prep: Wc = W0@W1, bc = b0@W1, WbT
    k_prep<<<32, 256>>>(W0, b0, W1, Wb);

    // g1 = (x@Wc + bc)*dinv -> d_Gh (fp16), seeds acc1 f32
    gemmF<FDIM, 0><<<(N + 255) / 256, 256>>>(x, nullptr, nullptr, N);

    // conv1 aggregate: acc1[col] += g1[row]  (fp16 gather, f32 red)
    k_scatter<1><<<GS, 256>>>(eipos, Epos);

    // g2 = (relu(dinv*acc1 + b1) @ W2)*dinv -> d_Gh, seeds acc2
    gemmF<HDIM, 1><<<(N + 255) / 256, 256>>>(nullptr, W2, b1, N);

    // conv2 aggregate: acc2[col] += g2[row]
    k_scatter<2><<<GS, 256>>>(eipos, Epos);

    // H2 = dinv*acc2 + b2 (fp16 to d_Hh in loader); TD = H2@WbT -> d_TDh fp16
    gemmF<HDIM, 2><<<(N + 255) / 256, 256>>>(nullptr, nullptr, b2, N);

    // logits[e] = H2[src] · TD[dst] + bb   (fp16 tables, raw edge buffer)
    k_bilinear<<<GS, 256>>>(eip, Epred, bb, out);
}

// round 14
// speedup vs baseline: 1.0801x; 1.0801x over previous
#include <cuda_runtime.h>
#include <cuda_fp16.h>

#define NMAX 100000
#define EMAX 1700000
#define FDIM 128
#define HDIM 64

// ---------------- scratch (static device globals; no runtime alloc) -------
__device__ int    d_is32;                // 1 if edge buffers are int32
__device__ int    d_deg[NMAX];
__device__ __half d_Gh  [NMAX * HDIM];   // g1, then g2 (fp16 messages)
__device__ float  d_ACC [NMAX * HDIM];   // acc1 (seeded with g1), f32
__device__ float  d_ACC2[NMAX * HDIM];   // acc2 (seeded with g2), f32
__device__ __half d_Hh  [NMAX * HDIM];   // H2 in fp16 (gemm3 A-loader side-store)
__device__ __half d_TDh [NMAX * HDIM];   // TD = H2 @ Wb^T in fp16
__device__ float  d_Wc  [FDIM * HDIM];   // W0 @ W1
__device__ float  d_bc  [HDIM];          // b0 @ W1
__device__ float  d_WbT [HDIM * HDIM];   // Wb[0]^T

// ---------------- helpers ---------------------------------------------------
__device__ __forceinline__ void red_add_v4(float* p, float4 v) {
#if __CUDA_ARCH__ >= 900
    asm volatile("red.global.add.v4.f32 [%0], {%1, %2, %3, %4};"
                 :: "l"(p), "f"(v.x), "f"(v.y), "f"(v.z), "f"(v.w)
                 : "memory");
#else
    atomicAdd(p + 0, v.x); atomicAdd(p + 1, v.y);
    atomicAdd(p + 2, v.z); atomicAdd(p + 3, v.w);
#endif
}

__device__ __forceinline__ float dinv_of(int r) {
    return rsqrtf((float)(d_deg[r] + 1));   // +1 self loop
}

// ---------------- init: zero deg + dtype detect (fused) ---------------------
// int64 LE with ids < 2^31 => every odd 32-bit word == 0; int32 => odd words
// are node ids (P(2048 sampled all zero) ~ 0).
__global__ void __launch_bounds__(256) k_init(const unsigned int* __restrict__ w,
                                              int nwords2, int n) {
    int i = blockIdx.x * blockDim.x + threadIdx.x;
    if (i == 0) d_is32 = 0;
    if (i < n) d_deg[i] = 0;
    int idx = 2 * i + 1;
    if (i < 2048 && idx < nwords2 && w[idx] != 0u) d_is32 = 1;
}

// ---------------- degree count ∥ weight prep (one kernel, disjoint blocks) --
// Blocks [0, degBlocks): count target degrees from raw edge buffer.
// Blocks [degBlocks, degBlocks+32): Wc = W0@W1, bc = b0@W1, WbT (independent).
__global__ void __launch_bounds__(256) k_degprep(const int* __restrict__ buf, int E,
                                                 int degBlocks,
                                                 const float* __restrict__ W0,
                                                 const float* __restrict__ b0,
                                                 const float* __restrict__ W1,
                                                 const float* __restrict__ Wb) {
    if ((int)blockIdx.x < degBlocks) {
        int i = blockIdx.x * blockDim.x + threadIdx.x;
        if (i >= E) return;
        int v = d_is32 ? buf[E + i] : buf[2 * (E + i)];
        atomicAdd(&d_deg[v], 1);
    } else {
        int t = (blockIdx.x - degBlocks) * blockDim.x + threadIdx.x;
        if (t < FDIM * HDIM) {
            int k = t / HDIM, o = t % HDIM;
            float s = 0.f;
            #pragma unroll 8
            for (int m = 0; m < FDIM; m++) s += W0[k * FDIM + m] * W1[m * HDIM + o];
            d_Wc[t] = s;
        }
        if (t < HDIM) {
            float s = 0.f;
            for (int m = 0; m < FDIM; m++) s += b0[m] * W1[m * HDIM + t];
            d_bc[t] = s;
        }
        if (t < HDIM * HDIM) {
            int i = t / HDIM, j = t % HDIM;
            d_WbT[j * HDIM + i] = Wb[t];   // WbT[j][i] = Wb[i][j]
        }
    }
}

// ---------------- fused GEMM: C[M,64] = f(A)[M,K] @ B[K,64] ---------------
// (R12 geometry: BM=64, 256 threads, 4x4 micro-tile — measured at roofline.)
// MODE 0: A = Ain (x), B = d_Wc.  C = (A@B + bc)*dinv -> d_Gh fp16 + d_ACC seed
// MODE 1: A = relu(dinv*acc1 + b1) in loader, B = Bin (W2).
//         C = (A@B)*dinv -> d_Gh fp16 + d_ACC2 seed
// MODE 2: A = dinv*acc2 + b2 = H2 in loader (side-store fp16 d_Hh), B = d_WbT.
//         C = A@B -> d_TDh fp16
template <int K, int MODE>
__global__ void __launch_bounds__(256) gemmF(const float* __restrict__ Ain,
                                             const float* __restrict__ Bin,
                                             const float* __restrict__ bA,
                                             int M) {
    const float* B = (MODE == 0) ? d_Wc : (MODE == 2) ? d_WbT : Bin;

    __shared__ float Bs[K][68];
    __shared__ float As[16][68];
    const int tid = threadIdx.x;

    for (int idx = tid; idx < K * 16; idx += 256) {
        int k = idx >> 4, c4 = (idx & 15) << 2;
        float4 v = *(const float4*)(B + k * 64 + c4);
        *(float4*)&Bs[k][c4] = v;
    }

    const int bm = blockIdx.x * 64;
    const int tr = tid >> 4;
    const int tc = tid & 15;
    const int lrow = tid >> 2;
    const int lk   = (tid & 3) << 2;

    float acc[4][4] = {};

    for (int kc = 0; kc < K; kc += 16) {
        float4 av = make_float4(0.f, 0.f, 0.f, 0.f);
        int grow = bm + lrow;
        if (grow < M) {
            if (MODE == 0) {
                av = *(const float4*)(Ain + (size_t)grow * K + kc + lk);
            } else {
                const float* accsrc = (MODE == 1) ? d_ACC : d_ACC2;
                float4 a4 = *(const float4*)(accsrc + (size_t)grow * 64 + kc + lk);
                float4 bv = *(const float4*)(bA + kc + lk);
                float s = dinv_of(grow);
                av.x = s * a4.x + bv.x;
                av.y = s * a4.y + bv.y;
                av.z = s * a4.z + bv.z;
                av.w = s * a4.w + bv.w;
                if (MODE == 1) {
                    av.x = fmaxf(av.x, 0.f); av.y = fmaxf(av.y, 0.f);
                    av.z = fmaxf(av.z, 0.f); av.w = fmaxf(av.w, 0.f);
                }
                if (MODE == 2) {   // side-store H2 fp16 (once per element)
                    __half2 h01 = __floats2half2_rn(av.x, av.y);
                    __half2 h23 = __floats2half2_rn(av.z, av.w);
                    uint2 pk = make_uint2(*(unsigned*)&h01, *(unsigned*)&h23);
                    *(uint2*)(d_Hh + (size_t)grow * 64 + kc + lk) = pk;
                }
            }
        }
        __syncthreads();                 // prev chunk consumed
        As[lk + 0][lrow] = av.x;
        As[lk + 1][lrow] = av.y;
        As[lk + 2][lrow] = av.z;
        As[lk + 3][lrow] = av.w;
        __syncthreads();
        #pragma unroll
        for (int k = 0; k < 16; k++) {
            float4 a = *(const float4*)&As[k][tr * 4];
            float4 b = *(const float4*)&Bs[kc + k][tc * 4];
            acc[0][0] += a.x * b.x; acc[0][1] += a.x * b.y; acc[0][2] += a.x * b.z; acc[0][3] += a.x * b.w;
            acc[1][0] += a.y * b.x; acc[1][1] += a.y * b.y; acc[1][2] += a.y * b.z; acc[1][3] += a.y * b.w;
            acc[2][0] += a.z * b.x; acc[2][1] += a.z * b.y; acc[2][2] += a.z * b.z; acc[2][3] += a.z * b.w;
            acc[3][0] += a.w * b.x; acc[3][1] += a.w * b.y; acc[3][2] += a.w * b.z; acc[3][3] += a.w * b.w;
        }
    }

    #pragma unroll
    for (int i = 0; i < 4; i++) {
        int r = bm + tr * 4 + i;
        if (r >= M) continue;
        float s = (MODE == 2) ? 1.f : dinv_of(r);
        #pragma unroll
        for (int j = 0; j < 4; j++) {
            float v = acc[i][j];
            if (MODE == 0) v += d_bc[tc * 4 + j];
            acc[i][j] = v * s;
        }
        size_t o = (size_t)r * 64 + tc * 4;
        if (MODE == 0 || MODE == 1) {
            __half2 h01 = __floats2half2_rn(acc[i][0], acc[i][1]);
            __half2 h23 = __floats2half2_rn(acc[i][2], acc[i][3]);
            uint2 pk = make_uint2(*(unsigned*)&h01, *(unsigned*)&h23);
            *(uint2*)(d_Gh + o) = pk;                     // fp16 messages
            float* accdst = (MODE == 0) ? d_ACC : d_ACC2;
            *(float4*)(accdst + o) = *(float4*)acc[i];    // f32 seed (self-loop)
        }
        if (MODE == 2) {                                  // TD in fp16
            __half2 h01 = __floats2half2_rn(acc[i][0], acc[i][1]);
            __half2 h23 = __floats2half2_rn(acc[i][2], acc[i][3]);
            uint2 pk = make_uint2(*(unsigned*)&h01, *(unsigned*)&h23);
            *(uint2*)(d_TDh + o) = pk;
        }
    }
}

// ---------------- edge scatter-add: acc[col] += g[row] --------------------
// 16 threads/edge: gather 4 halves (8B), convert, ONE red.v4.f32 (16B).
template <int WHICH>   // 1 -> d_ACC, 2 -> d_ACC2
__global__ void __launch_bounds__(256) k_scatter(const int* __restrict__ buf, int E) {
    const int is32 = d_is32;
    int total = E * 16;
    for (int t = blockIdx.x * blockDim.x + threadIdx.x; t < total;
         t += gridDim.x * blockDim.x) {
        int e = t >> 4, c = t & 15;
        int r  = __ldg(&buf[is32 ? e : 2 * e]);
        int cl = __ldg(&buf[is32 ? (E + e) : 2 * (E + e)]);
        uint2 pk = __ldg((const uint2*)(d_Gh + (size_t)r * 64 + c * 4));
        float2 f01 = __half22float2(*(__half2*)&pk.x);
        float2 f23 = __half22float2(*(__half2*)&pk.y);
        float4 v = make_float4(f01.x, f01.y, f23.x, f23.y);
        float* p = (WHICH == 1 ? d_ACC : d_ACC2) + (size_t)cl * 64 + c * 4;
        red_add_v4(p, v);
    }
}

// ---------------- bilinear decoder: out[e] = H2[src]·TD[dst] + bb ---------
__global__ void __launch_bounds__(256) k_bilinear(const int* __restrict__ buf, int E,
                                                  const float* __restrict__ bb,
                                                  float* __restrict__ out) {
    const int is32 = d_is32;
    const float bias = bb[0];
    const uint4* Hp = (const uint4*)d_Hh;    // 8 halves per uint4
    const uint4* Tp = (const uint4*)d_TDh;
    int total = E * 8;
    for (int t = blockIdx.x * blockDim.x + threadIdx.x; t < total;
         t += gridDim.x * blockDim.x) {
        int e = t >> 3, c = t & 7;
        int s = __ldg(&buf[is32 ? e : 2 * e]);
        int d = __ldg(&buf[is32 ? (E + e) : 2 * (E + e)]);
        uint4 a = __ldg(Hp + (size_t)s * 8 + c);
        uint4 b = __ldg(Tp + (size_t)d * 8 + c);
        float p = 0.f;
        {
            float2 fa, fb;
            fa = __half22float2(*(__half2*)&a.x); fb = __half22float2(*(__half2*)&b.x);
            p += fa.x * fb.x + fa.y * fb.y;
            fa = __half22float2(*(__half2*)&a.y); fb = __half22float2(*(__half2*)&b.y);
            p += fa.x * fb.x + fa.y * fb.y;
            fa = __half22float2(*(__half2*)&a.z); fb = __half22float2(*(__half2*)&b.z);
            p += fa.x * fb.x + fa.y * fb.y;
            fa = __half22float2(*(__half2*)&a.w); fb = __half22float2(*(__half2*)&b.w);
            p += fa.x * fb.x + fa.y * fb.y;
        }
        p += __shfl_xor_sync(0xffffffffu, p, 4);
        p += __shfl_xor_sync(0xffffffffu, p, 2);
        p += __shfl_xor_sync(0xffffffffu, p, 1);
        if (c == 0) out[e] = p + bias;
    }
}

// ---------------- launcher: kernel launches ONLY ---------------------------
extern "C" void kernel_launch(void* const* d_in, const int* in_sizes, int n_in,
                              void* d_out, int out_size) {
    const float* x     = (const float*)d_in[0];
    const int*   eip   = (const int*)d_in[1];    // prediction edges (raw words)
    const int*   eipos = (const int*)d_in[2];    // message edges (raw words)
    const float* W0    = (const float*)d_in[3];
    const float* b0    = (const float*)d_in[4];
    const float* W1    = (const float*)d_in[5];
    const float* b1    = (const float*)d_in[6];
    const float* W2    = (const float*)d_in[7];
    const float* b2    = (const float*)d_in[8];
    const float* Wb    = (const float*)d_in[9];
    const float* bb    = (const float*)d_in[10];
    float* out = (float*)d_out;

    const int N     = in_sizes[0] / FDIM;
    const int Epred = in_sizes[1] / 2;
    const int Epos  = in_sizes[2] / 2;
    const int GS    = 8192;

    // init (zero deg + dtype detect)
    k_init<<<(N + 255) / 256, 256>>>((const unsigned int*)eip, 2 * Epred, N);

    // degree count ∥ weight prep (independent work, one kernel)
    int degBlocks = (Epos + 255) / 256;
    k_degprep<<<degBlocks + 32, 256>>>(eipos, Epos, degBlocks, W0, b0, W1, Wb);

    // g1 = (x@Wc + bc)*dinv -> d_Gh (fp16), seeds acc1 f32  (dinv inline)
    gemmF<FDIM, 0><<<(N + 63) / 64, 256>>>(x, nullptr, nullptr, N);

    // conv1 aggregate: acc1[col] += g1[row]  (fp16 gather, f32 red)
    k_scatter<1><<<GS, 256>>>(eipos, Epos);

    // g2 = (relu(dinv*acc1 + b1) @ W2)*dinv -> d_Gh, seeds acc2
    gemmF<HDIM, 1><<<(N + 63) / 64, 256>>>(nullptr, W2, b1, N);

    // conv2 aggregate: acc2[col] += g2[row]
    k_scatter<2><<<GS, 256>>>(eipos, Epos);

    // H2 = dinv*acc2 + b2 (fp16 to d_Hh in loader); TD = H2@WbT -> d_TDh fp16
    gemmF<HDIM, 2><<<(N + 63) / 64, 256>>>(nullptr, nullptr, b2, N);

    // logits[e] = H2[src] · TD[dst] + bb   (fp16 tables, raw edge buffer)
    k_bilinear<<<GS, 256>>>(eip, Epred, bb, out);
}